// round 16
// baseline (speedup 1.0000x reference)
#include <cuda_runtime.h>
#include <cuda_fp16.h>
#include <math.h>

#define BB 4
#define NN 512
#define BN 2048
#define TT 64
#define DD 128
#define HH 4
#define HD 32
#define EPS 1e-5f
#define LSLOPE 0.2f
#define NSM 148

__device__ __half g_h[BN * TT * DD];
__device__ __half g_ret[BN * TT * DD];
__device__ __half g_x16[BN * TT * 16];
__device__ __half g_adjn[BB * NN * NN];
__device__ __half g_adj2[BB * NN * NN];
__device__ __half g_hlT[BB * DD * NN];
__device__ __half g_cur_a[BB * NN * DD];
__device__ __half g_cur_b[BB * NN * DD];
__device__ float g_bias2[BN * DD];

__device__ __forceinline__ float lrelu(float v) { return v > 0.f ? v : LSLOPE * v; }
__device__ __forceinline__ unsigned ldh2(const __half* p) { return *(const unsigned*)p; }
__device__ __forceinline__ void sth2(__half* p, float a, float b) {
    *(__half2*)p = __floats2half2_rn(a, b);
}

#define MMA_F16(C, A0, A1, A2, A3, B0, B1)                                              \
    asm volatile(                                                                       \
        "mma.sync.aligned.m16n8k16.row.col.f32.f16.f16.f32 "                            \
        "{%0,%1,%2,%3},{%4,%5,%6,%7},{%8,%9},{%0,%1,%2,%3};"                            \
        : "+f"((C)[0]), "+f"((C)[1]), "+f"((C)[2]), "+f"((C)[3])                        \
        : "r"(A0), "r"(A1), "r"(A2), "r"(A3), "r"(B0), "r"(B1))

__device__ __forceinline__ void ldsmx4(unsigned r[4], unsigned addr) {
    asm volatile("ldmatrix.sync.aligned.m8n8.x4.shared.b16 {%0,%1,%2,%3}, [%4];"
                 : "=r"(r[0]), "=r"(r[1]), "=r"(r[2]), "=r"(r[3]) : "r"(addr));
}
__device__ __forceinline__ void ldsmx4t(unsigned r[4], unsigned addr) {
    asm volatile("ldmatrix.sync.aligned.m8n8.x4.trans.shared.b16 {%0,%1,%2,%3}, [%4];"
                 : "=r"(r[0]), "=r"(r[1]), "=r"(r[2]), "=r"(r[3]) : "r"(addr));
}
__device__ __forceinline__ void ldsmx2(unsigned& r0, unsigned& r1, unsigned addr) {
    asm volatile("ldmatrix.sync.aligned.m8n8.x2.shared.b16 {%0,%1}, [%2];"
                 : "=r"(r0), "=r"(r1) : "r"(addr));
}
#define CP_ASYNC16(dst, src)                                                            \
    asm volatile("cp.async.cg.shared.global [%0], [%1], 16;" ::"r"(dst), "l"(src))
#define CP_COMMIT() asm volatile("cp.async.commit_group;")
#define CP_WAIT0() asm volatile("cp.async.wait_group 0;")

#define RW 136
#define QBW 392

#define DLA(lane, S) ((((lane) & 15) * (S) + ((lane) >> 4) * 8) * 2)
#define DLB(lane, S) ((((lane) & 7) * (S) + (((lane) >> 3) & 1) * 8) * 2)

// ---------------- x -> fp16 padded [64][16] ----------------
__global__ void k_x16(const float* __restrict__ x) {
    int bn = blockIdx.x;
    int tid = threadIdx.x;
    const float* xb = x + (size_t)bn * TT * 8;
    __half* ob = g_x16 + (size_t)bn * TT * 16;
    for (int e = tid; e < 1024; e += 128) {
        int t = e >> 4, f = e & 15;
        ob[e] = (f < 8) ? __float2half(xb[t * 8 + f]) : __half(0);
    }
}

// ---------------- adj row-normalize ----------------
__global__ void k_adjn(const float* __restrict__ adj) {
    int row = blockIdx.x;
    __shared__ float red[8];
    const float* ar = adj + (size_t)row * NN;
    float s = 0.f;
    for (int j = threadIdx.x; j < NN; j += 256) s += ar[j];
#pragma unroll
    for (int o = 16; o; o >>= 1) s += __shfl_down_sync(0xffffffffu, s, o);
    if ((threadIdx.x & 31) == 0) red[threadIdx.x >> 5] = s;
    __syncthreads();
    if (threadIdx.x == 0) {
        float t = 0.f;
#pragma unroll
        for (int w = 0; w < 8; w++) t += red[w];
        red[0] = 1.0f / (t + 1e-9f);
    }
    __syncthreads();
    float inv = red[0];
    for (int j = threadIdx.x; j < NN; j += 256)
        g_adjn[(size_t)row * NN + j] = __float2half(ar[j] * inv);
}

// ---------------- A2 = A@A ----------------
__global__ void __launch_bounds__(256, 4) k_a2() {
    __shared__ __half As[64 * 72];
    __shared__ __half Bs[64 * 72];
    int tid = threadIdx.x, lane = tid & 31, w = tid >> 5, g = lane >> 2, tg = lane & 3;
    int m0 = blockIdx.x * 64, n0 = blockIdx.y * 64, b = blockIdx.z;
    const __half* adjb = g_adjn + (size_t)b * NN * NN;
    int mt = w & 3, nh = w >> 2;

    float c[4][4];
#pragma unroll
    for (int nt = 0; nt < 4; nt++)
#pragma unroll
        for (int ci = 0; ci < 4; ci++) c[nt][ci] = 0.f;

    for (int kc = 0; kc < 8; kc++) {
        __syncthreads();
        for (int e = tid; e < 512; e += 256) {
            int r = e >> 3, u = e & 7;
            *(uint4*)(As + r * 72 + u * 8) =
                *(const uint4*)(adjb + (size_t)(m0 + r) * NN + kc * 64 + u * 8);
        }
        for (int e = tid; e < 512; e += 256) {
            int kr = e >> 3, u = e & 7;
            uint4 raw = *(const uint4*)(adjb + (size_t)(kc * 64 + kr) * NN + n0 + u * 8);
            const __half* hp = (const __half*)&raw;
#pragma unroll
            for (int j = 0; j < 8; j++) Bs[(u * 8 + j) * 72 + kr] = hp[j];
        }
        __syncthreads();
#pragma unroll
        for (int ks2 = 0; ks2 < 4; ks2++) {
            int off = ks2 * 16;
            const __half* ar0 = As + (mt * 16 + g) * 72 + off + 2 * tg;
            const __half* ar1 = ar0 + 8 * 72;
            unsigned a0 = ldh2(ar0), a1 = ldh2(ar1);
            unsigned a2 = ldh2(ar0 + 8), a3 = ldh2(ar1 + 8);
#pragma unroll
            for (int nt = 0; nt < 4; nt++) {
                const __half* br = Bs + (nh * 32 + nt * 8 + g) * 72 + off + 2 * tg;
                unsigned b0 = ldh2(br), b1 = ldh2(br + 8);
                MMA_F16(c[nt], a0, a1, a2, a3, b0, b1);
            }
        }
    }
    __half* out = g_adj2 + (size_t)b * NN * NN;
#pragma unroll
    for (int nt = 0; nt < 4; nt++) {
        int col = n0 + nh * 32 + nt * 8 + 2 * tg;
        int r0 = m0 + mt * 16 + g, r1 = r0 + 8;
        sth2(&out[(size_t)r0 * NN + col], c[nt][0], c[nt][1]);
        sth2(&out[(size_t)r1 * NN + col], c[nt][2], c[nt][3]);
    }
}

// ---------------- fused retention (lay0 factored QKV + triangular skip) ----------------
#define O_HB0 0
#define O_HB1 8704
#define O_QS 17408
#define O_KS 26112
#define O_VS 34816
#define O_BC 43520
#define O_QB 52736
#define RET_HALVES 77824
#define RET_SMEM (RET_HALVES * 2)

__global__ void __launch_bounds__(512, 1) k_ret(
    const float* __restrict__ wq, const float* __restrict__ bq,
    const float* __restrict__ wk, const float* __restrict__ bk,
    const float* __restrict__ wv, const float* __restrict__ bv,
    const float* __restrict__ gnw, const float* __restrict__ gnb,
    const float* __restrict__ gam,
    const float* __restrict__ lnw, const float* __restrict__ lnb,
    const float* __restrict__ pw, const float* __restrict__ pb,
    const float* __restrict__ pos, int lay0) {
    extern __shared__ unsigned char smraw[];
    __half* smh = (__half*)smraw;
    __half* ws = smh;
    __half* Qs = smh + O_QS;
    __half* Ks = smh + O_KS;
    __half* Vs = smh + O_VS;
    __half* BcS = smh + O_BC;
    __half* QbS = smh + O_QB;
    __shared__ float cbias[384];
    __shared__ float gpow[64];
    __shared__ float shead[8];
    __shared__ float sum1[64], sum2[64];
    __shared__ float sgw[128], sgb[128], slw[128], slb[128];
    __shared__ float pwsm[128 * 8];

    int tid = threadIdx.x, lane = tid & 31, w = tid >> 5, g = lane >> 2, tg = lane & 3;

    unsigned sb_base = (unsigned)__cvta_generic_to_shared(smh);
    unsigned sb_hb[2] = {sb_base + O_HB0 * 2, sb_base + O_HB1 * 2};
    unsigned sb_qs = sb_base + O_QS * 2;
    unsigned sb_ks = sb_base + O_KS * 2;
    unsigned sb_vs = sb_base + O_VS * 2;
    unsigned dA_RW = DLA(lane, RW), dB_RW = DLB(lane, RW);
    unsigned dA24 = DLA(lane, 24), dB24 = DLB(lane, 24);

    for (int e = tid; e < 12288; e += 512) {
        int r = e >> 5, k4 = (e & 31) * 4;
        const float* src = (r < 128) ? (wq + r * DD)
                         : (r < 256) ? (wk + (r - 128) * DD)
                                     : (wv + (r - 256) * DD);
        float4 v = *(const float4*)(src + k4);
        __half* dst = ws + r * RW + k4;
        sth2(dst, v.x, v.y);
        sth2(dst + 2, v.z, v.w);
    }
    for (int e = tid; e < 384; e += 512)
        cbias[e] = e < 128 ? bq[e] : (e < 256 ? bk[e - 128] : bv[e - 256]);
    if (tid < 64) gpow[tid] = powf(gam[0], (float)tid);
    if (tid < 128) {
        sgw[tid] = gnw[tid];
        sgb[tid] = gnb[tid];
        slw[tid] = lnw[tid];
        slb[tid] = lnb[tid];
    }
    unsigned Breg[8][3][2];

    if (lay0) {
        for (int e = tid; e < 1024; e += 512) pwsm[e] = pw[e];
        for (int e = tid; e < 4096; e += 512) {
            int t = e >> 6, d2 = (e & 63) * 2;
            float a = pos[t * DD + d2] + pb[d2];
            float b = pos[t * DD + d2 + 1] + pb[d2 + 1];
            sth2(&QbS[t * RW + d2], a, b);
        }
        __syncthreads();
        float qc[4][3][4];
#pragma unroll
        for (int m2 = 0; m2 < 4; m2++)
#pragma unroll
            for (int nt = 0; nt < 3; nt++)
#pragma unroll
                for (int ci = 0; ci < 4; ci++) qc[m2][nt][ci] = 0.f;
#pragma unroll
        for (int ks2 = 0; ks2 < 8; ks2++) {
            int off = ks2 * 16;
            unsigned a[4][4];
#pragma unroll
            for (int m2 = 0; m2 < 4; m2++)
                ldsmx4(a[m2], sb_base + (O_QB + (m2 * 16) * RW + off) * 2 + dA_RW);
#pragma unroll
            for (int nt = 0; nt < 3; nt++) {
                unsigned b0, b1;
                ldsmx2(b0, b1, sb_base + ((w * 24 + nt * 8) * RW + off) * 2 + dB_RW);
#pragma unroll
                for (int m2 = 0; m2 < 4; m2++)
                    MMA_F16(qc[m2][nt], a[m2][0], a[m2][1], a[m2][2], a[m2][3], b0, b1);
            }
        }
        float pacc[8];
#pragma unroll
        for (int f = 0; f < 8; f++) pacc[f] = 0.f;
        if (tid < 384) {
            for (int d = 0; d < 128; d++) {
                float wv2 = __half2float(ws[tid * RW + d]);
                float4 p0 = *(float4*)&pwsm[d * 8];
                float4 p1 = *(float4*)&pwsm[d * 8 + 4];
                pacc[0] += wv2 * p0.x; pacc[1] += wv2 * p0.y;
                pacc[2] += wv2 * p0.z; pacc[3] += wv2 * p0.w;
                pacc[4] += wv2 * p1.x; pacc[5] += wv2 * p1.y;
                pacc[6] += wv2 * p1.z; pacc[7] += wv2 * p1.w;
            }
        }
        __syncthreads();
        if (tid < 384) {
#pragma unroll
            for (int f = 0; f < 8; f++) BcS[tid * 24 + f] = __float2half(pacc[f]);
#pragma unroll
            for (int f = 8; f < 16; f++) BcS[tid * 24 + f] = __half(0);
        }
#pragma unroll
        for (int m2 = 0; m2 < 4; m2++) {
            int r0e = m2 * 16 + g, r1e = r0e + 8;
#pragma unroll
            for (int nt = 0; nt < 3; nt++) {
                int gc0 = w * 24 + nt * 8 + 2 * tg;
                sth2(&QbS[r0e * QBW + gc0], qc[m2][nt][0] + cbias[gc0],
                     qc[m2][nt][1] + cbias[gc0 + 1]);
                sth2(&QbS[r1e * QBW + gc0], qc[m2][nt][2] + cbias[gc0],
                     qc[m2][nt][3] + cbias[gc0 + 1]);
            }
        }
        __syncthreads();
        ldsmx2(Breg[0][0][0], Breg[0][0][1], sb_base + (O_BC + (w * 24 + 0) * 24) * 2 + dB24);
        ldsmx2(Breg[0][1][0], Breg[0][1][1], sb_base + (O_BC + (w * 24 + 8) * 24) * 2 + dB24);
        ldsmx2(Breg[0][2][0], Breg[0][2][1], sb_base + (O_BC + (w * 24 + 16) * 24) * 2 + dB24);
    } else {
        __syncthreads();
#pragma unroll
        for (int ks2 = 0; ks2 < 8; ks2++)
#pragma unroll
            for (int nt = 0; nt < 3; nt++)
                ldsmx2(Breg[ks2][nt][0], Breg[ks2][nt][1],
                       sb_base + ((w * 24 + nt * 8) * RW + ks2 * 16) * 2 + dB_RW);
        __syncthreads();
    }

    // retention map: heavy row-tiles spread across SMSPs
    int hh = w & 3, mt = w >> 2;
    int bid = blockIdx.x;
    int s0 = (int)(((long)bid * BN) / NSM);
    int s1 = (int)(((long)bid + 1) * BN / NSM);

    if (lay0) {
        if (tid < 128) {
            int r = tid >> 1, hc = (tid & 1) * 8;
            CP_ASYNC16(sb_hb[0] + (r * 24 + hc) * 2, g_x16 + (size_t)s0 * 1024 + r * 16 + hc);
        }
    } else {
        int r = tid >> 4, c8 = (tid & 15) * 8;
        const __half* src = g_h + (size_t)s0 * (TT * DD);
        CP_ASYNC16(sb_hb[0] + (r * RW + c8) * 2, src + r * DD + c8);
        CP_ASYNC16(sb_hb[0] + ((r + 32) * RW + c8) * 2, src + (r + 32) * DD + c8);
    }
    CP_COMMIT();

    for (int s = s0; s < s1; s++) {
        int cur = (s - s0) & 1;
        CP_WAIT0();
        __syncthreads();  // [B1]
        if (tid < 64) { sum1[tid] = 0.f; sum2[tid] = 0.f; }
        if (tid < 8) shead[tid] = 0.f;
        if (s + 1 < s1) {
            unsigned db = sb_hb[cur ^ 1];
            if (lay0) {
                if (tid < 128) {
                    int r = tid >> 1, hc = (tid & 1) * 8;
                    CP_ASYNC16(db + (r * 24 + hc) * 2,
                               g_x16 + (size_t)(s + 1) * 1024 + r * 16 + hc);
                }
            } else {
                int r = tid >> 4, c8 = (tid & 15) * 8;
                const __half* src = g_h + (size_t)(s + 1) * (TT * DD);
                CP_ASYNC16(db + (r * RW + c8) * 2, src + r * DD + c8);
                CP_ASYNC16(db + ((r + 32) * RW + c8) * 2, src + (r + 32) * DD + c8);
            }
        }
        CP_COMMIT();

        // ---- QKV
        float c[4][3][4];
#pragma unroll
        for (int m2 = 0; m2 < 4; m2++)
#pragma unroll
            for (int nt = 0; nt < 3; nt++)
#pragma unroll
                for (int ci = 0; ci < 4; ci++) c[m2][nt][ci] = 0.f;
        if (lay0) {
            unsigned a[4][4];
#pragma unroll
            for (int m2 = 0; m2 < 4; m2++)
                ldsmx4(a[m2], sb_hb[cur] + ((m2 * 16) * 24) * 2 + dA24);
#pragma unroll
            for (int m2 = 0; m2 < 4; m2++)
#pragma unroll
                for (int nt = 0; nt < 3; nt++)
                    MMA_F16(c[m2][nt], a[m2][0], a[m2][1], a[m2][2], a[m2][3],
                            Breg[0][nt][0], Breg[0][nt][1]);
        } else {
#pragma unroll
            for (int ks2 = 0; ks2 < 8; ks2++) {
                int off = ks2 * 16;
                unsigned a[4][4];
#pragma unroll
                for (int m2 = 0; m2 < 4; m2++)
                    ldsmx4(a[m2], sb_hb[cur] + ((m2 * 16) * RW + off) * 2 + dA_RW);
#pragma unroll
                for (int m2 = 0; m2 < 4; m2++)
#pragma unroll
                    for (int nt = 0; nt < 3; nt++)
                        MMA_F16(c[m2][nt], a[m2][0], a[m2][1], a[m2][2], a[m2][3],
                                Breg[ks2][nt][0], Breg[ks2][nt][1]);
            }
        }

#pragma unroll
        for (int m2 = 0; m2 < 4; m2++) {
            int r0e = m2 * 16 + g, r1e = r0e + 8;
#pragma unroll
            for (int nt = 0; nt < 3; nt++) {
                int gc0 = w * 24 + nt * 8 + 2 * tg;
                float b00, b01, b10, b11;
                if (lay0) {
                    unsigned p0 = ldh2(&QbS[r0e * QBW + gc0]);
                    unsigned p1 = ldh2(&QbS[r1e * QBW + gc0]);
                    __half2 h0 = *(__half2*)&p0, h1 = *(__half2*)&p1;
                    b00 = __low2float(h0); b01 = __high2float(h0);
                    b10 = __low2float(h1); b11 = __high2float(h1);
                } else {
                    b00 = b10 = cbias[gc0];
                    b01 = b11 = cbias[gc0 + 1];
                }
                float v00 = c[m2][nt][0] + b00, v01 = c[m2][nt][1] + b01;
                float v10 = c[m2][nt][2] + b10, v11 = c[m2][nt][3] + b11;
                if (gc0 < 128) {
                    sth2(&Qs[r0e * RW + gc0], v00, v01);
                    sth2(&Qs[r1e * RW + gc0], v10, v11);
                } else if (gc0 < 256) {
                    int k0 = gc0 - 128;
                    sth2(&Ks[r0e * RW + k0], v00, v01);
                    sth2(&Ks[r1e * RW + k0], v10, v11);
                } else {
                    int d0 = gc0 - 256;
                    sth2(&Vs[r0e * RW + d0], v00, v01);
                    sth2(&Vs[r1e * RW + d0], v10, v11);
                }
            }
        }
        __syncthreads();  // [B2]

        // ---- S = Q K^T (triangular: np <= mt only)
        unsigned qa[2][4];
        ldsmx4(qa[0], sb_qs + ((mt * 16) * RW + hh * 32) * 2 + dA_RW);
        ldsmx4(qa[1], sb_qs + ((mt * 16) * RW + hh * 32 + 16) * 2 + dA_RW);
        float scC[8][4];
#pragma unroll
        for (int nt = 0; nt < 8; nt++)
#pragma unroll
            for (int ci = 0; ci < 4; ci++) scC[nt][ci] = 0.f;
#pragma unroll
        for (int ks2 = 0; ks2 < 2; ks2++) {
            int off = hh * 32 + ks2 * 16;
#pragma unroll
            for (int np = 0; np < 4; np++) {
                if (np <= mt) {
                    unsigned bb[4];
                    ldsmx4(bb, sb_ks + ((np * 16) * RW + off) * 2 + dA_RW);
                    MMA_F16(scC[np * 2], qa[ks2][0], qa[ks2][1], qa[ks2][2], qa[ks2][3],
                            bb[0], bb[2]);
                    MMA_F16(scC[np * 2 + 1], qa[ks2][0], qa[ks2][1], qa[ks2][2], qa[ks2][3],
                            bb[1], bb[3]);
                }
            }
        }
        unsigned sa[4][4];
        {
            int q0 = mt * 16 + g, q1 = q0 + 8;
#pragma unroll
            for (int j = 0; j < 4; j++) {
                if (j <= mt) {
                    int k0 = (2 * j) * 8 + 2 * tg;
                    int k1 = k0 + 8;
                    float v00 = (k0 <= q0) ? scC[2 * j][0] * gpow[q0 - k0] : 0.f;
                    float v01 = (k0 + 1 <= q0) ? scC[2 * j][1] * gpow[q0 - k0 - 1] : 0.f;
                    float v10 = (k0 <= q1) ? scC[2 * j][2] * gpow[q1 - k0] : 0.f;
                    float v11 = (k0 + 1 <= q1) ? scC[2 * j][3] * gpow[q1 - k0 - 1] : 0.f;
                    float u00 = (k1 <= q0) ? scC[2 * j + 1][0] * gpow[q0 - k1] : 0.f;
                    float u01 = (k1 + 1 <= q0) ? scC[2 * j + 1][1] * gpow[q0 - k1 - 1] : 0.f;
                    float u10 = (k1 <= q1) ? scC[2 * j + 1][2] * gpow[q1 - k1] : 0.f;
                    float u11 = (k1 + 1 <= q1) ? scC[2 * j + 1][3] * gpow[q1 - k1 - 1] : 0.f;
                    __half2 t0 = __floats2half2_rn(v00, v01);
                    __half2 t1 = __floats2half2_rn(v10, v11);
                    __half2 t2 = __floats2half2_rn(u00, u01);
                    __half2 t3 = __floats2half2_rn(u10, u11);
                    sa[j][0] = *(unsigned*)&t0;
                    sa[j][1] = *(unsigned*)&t1;
                    sa[j][2] = *(unsigned*)&t2;
                    sa[j][3] = *(unsigned*)&t3;
                }
            }
        }

        // ---- O = S V (triangular: j <= mt only)
        float oc[4][4];
#pragma unroll
        for (int nt = 0; nt < 4; nt++)
#pragma unroll
            for (int ci = 0; ci < 4; ci++) oc[nt][ci] = 0.f;
#pragma unroll
        for (int j = 0; j < 4; j++) {
            if (j <= mt) {
#pragma unroll
                for (int np = 0; np < 2; np++) {
                    unsigned bb[4];
                    ldsmx4t(bb, sb_vs + ((j * 16) * RW + hh * 32 + np * 16) * 2 + dA_RW);
                    MMA_F16(oc[np * 2], sa[j][0], sa[j][1], sa[j][2], sa[j][3], bb[0], bb[1]);
                    MMA_F16(oc[np * 2 + 1], sa[j][0], sa[j][1], sa[j][2], sa[j][3], bb[2],
                            bb[3]);
                }
            }
        }
        {
            float s1v = 0.f, s2v = 0.f;
#pragma unroll
            for (int nt = 0; nt < 4; nt++)
#pragma unroll
                for (int ci = 0; ci < 4; ci++) {
                    float v = oc[nt][ci];
                    s1v += v; s2v += v * v;
                }
#pragma unroll
            for (int o = 16; o; o >>= 1) {
                s1v += __shfl_xor_sync(0xffffffffu, s1v, o);
                s2v += __shfl_xor_sync(0xffffffffu, s2v, o);
            }
            if (lane == 0) {
                atomicAdd(&shead[hh * 2], s1v);
                atomicAdd(&shead[hh * 2 + 1], s2v);
            }
        }
        __syncthreads();  // [B3]

        float mn, rs;
        {
            mn = shead[hh * 2] * (1.0f / 2048.0f);
            float var = shead[hh * 2 + 1] * (1.0f / 2048.0f) - mn * mn;
            rs = rsqrtf(var + EPS);
        }
        float p1[2] = {0.f, 0.f}, p2[2] = {0.f, 0.f};
#pragma unroll
        for (int nt = 0; nt < 4; nt++)
#pragma unroll
            for (int ci = 0; ci < 4; ci++) {
                int col = hh * 32 + nt * 8 + 2 * tg + (ci & 1);
                float v = (oc[nt][ci] - mn) * rs * sgw[col] + sgb[col];
                oc[nt][ci] = v;
                int hf = (ci >= 2) ? 1 : 0;
                p1[hf] += v;
                p2[hf] += v * v;
            }
#pragma unroll
        for (int o = 1; o <= 2; o <<= 1) {
            p1[0] += __shfl_xor_sync(0xffffffffu, p1[0], o);
            p1[1] += __shfl_xor_sync(0xffffffffu, p1[1], o);
            p2[0] += __shfl_xor_sync(0xffffffffu, p2[0], o);
            p2[1] += __shfl_xor_sync(0xffffffffu, p2[1], o);
        }
        int r0 = mt * 16 + g, r1 = r0 + 8;
        if (tg == 0) {
            atomicAdd(&sum1[r0], p1[0]);
            atomicAdd(&sum2[r0], p2[0]);
            atomicAdd(&sum1[r1], p1[1]);
            atomicAdd(&sum2[r1], p2[1]);
        }
        __syncthreads();  // [B4]

        float mu0 = sum1[r0] * (1.0f / 128.0f);
        float rs0 = rsqrtf(sum2[r0] * (1.0f / 128.0f) - mu0 * mu0 + EPS);
        float mu1 = sum1[r1] * (1.0f / 128.0f);
        float rs1 = rsqrtf(sum2[r1] * (1.0f / 128.0f) - mu1 * mu1 + EPS);

        __half* go = g_ret + (size_t)s * (TT * DD);
        int bb2 = s >> 9, ii = s & 511;
#pragma unroll
        for (int nt = 0; nt < 4; nt++) {
            int cb = hh * 32 + nt * 8 + 2 * tg;
            float lw0 = slw[cb], lb0 = slb[cb];
            float lw1 = slw[cb + 1], lb1 = slb[cb + 1];
            float u0 = (oc[nt][0] - mu0) * rs0 * lw0 + lb0;
            float u1 = (oc[nt][1] - mu0) * rs0 * lw1 + lb1;
            float w1x = (oc[nt][2] - mu1) * rs1 * lw0 + lb0;
            float w1y = (oc[nt][3] - mu1) * rs1 * lw1 + lb1;
            sth2(&go[r0 * DD + cb], u0, u1);
            sth2(&go[r1 * DD + cb], w1x, w1y);
            if (r1 == 63) {
                g_hlT[((size_t)bb2 * DD + cb) * NN + ii] = __float2half(w1x);
                g_hlT[((size_t)bb2 * DD + cb + 1) * NN + ii] = __float2half(w1y);
            }
        }
    }
}

// ---------------- both diffusion hops via A2 (ldmatrix) ----------------
__global__ void __launch_bounds__(256, 2) k_hopP() {
    __shared__ __half Xs[2][128 * 72];
    __shared__ __half As[2][32 * 72];
    int tid = threadIdx.x, lane = tid & 31, w = tid >> 5;
    int g = lane >> 2, tg = lane & 3;
    int i0 = blockIdx.x * 32, b = blockIdx.y, which = blockIdx.z;
    const __half* M = (which ? g_adj2 : g_adjn) + (size_t)b * NN * NN;
    const __half* Xt = g_hlT + (size_t)b * DD * NN;
    __half* dst = (which ? g_cur_b : g_cur_a) + (size_t)b * NN * DD;

    unsigned sb_xs[2] = {(unsigned)__cvta_generic_to_shared(Xs[0]),
                         (unsigned)__cvta_generic_to_shared(Xs[1])};
    unsigned sb_as[2] = {(unsigned)__cvta_generic_to_shared(As[0]),
                         (unsigned)__cvta_generic_to_shared(As[1])};
    unsigned dA72 = DLA(lane, 72);

    int mt2 = w & 1, nh = w >> 1;
    float c[4][4];
#pragma unroll
    for (int nt = 0; nt < 4; nt++)
#pragma unroll
        for (int ci = 0; ci < 4; ci++) c[nt][ci] = 0.f;

#pragma unroll
    for (int i = 0; i < 4; i++) {
        int e = tid + i * 256;
        int r = e >> 3, u = e & 7;
        *(uint4*)(Xs[0] + r * 72 + u * 8) = *(const uint4*)(Xt + (size_t)r * NN + u * 8);
    }
    {
        int r = tid >> 3, u = tid & 7;
        *(uint4*)(As[0] + r * 72 + u * 8) =
            *(const uint4*)(M + (size_t)(i0 + r) * NN + u * 8);
    }
    __syncthreads();

#pragma unroll 1
    for (int kc = 0; kc < 8; kc++) {
        uint4 px[4], pa;
        if (kc < 7) {
            int k0 = (kc + 1) * 64;
#pragma unroll
            for (int i = 0; i < 4; i++) {
                int e = tid + i * 256;
                int r = e >> 3, u = e & 7;
                px[i] = *(const uint4*)(Xt + (size_t)r * NN + k0 + u * 8);
            }
            int r = tid >> 3, u = tid & 7;
            pa = *(const uint4*)(M + (size_t)(i0 + r) * NN + k0 + u * 8);
        }
        unsigned xb = sb_xs[kc & 1];
        unsigned ab = sb_as[kc & 1];
#pragma unroll
        for (int ks2 = 0; ks2 < 4; ks2++) {
            int off = ks2 * 16;
            unsigned a[4];
            ldsmx4(a, ab + ((mt2 * 16) * 72 + off) * 2 + dA72);
#pragma unroll
            for (int np = 0; np < 2; np++) {
                unsigned bb[4];
                ldsmx4(bb, xb + ((nh * 32 + np * 16) * 72 + off) * 2 + dA72);
                MMA_F16(c[np * 2], a[0], a[1], a[2], a[3], bb[0], bb[2]);
                MMA_F16(c[np * 2 + 1], a[0], a[1], a[2], a[3], bb[1], bb[3]);
            }
        }
        if (kc < 7) {
            __half* Xn = Xs[(kc + 1) & 1];
            __half* An = As[(kc + 1) & 1];
#pragma unroll
            for (int i = 0; i < 4; i++) {
                int e = tid + i * 256;
                int r = e >> 3, u = e & 7;
                *(uint4*)(Xn + r * 72 + u * 8) = px[i];
            }
            int r = tid >> 3, u = tid & 7;
            *(uint4*)(An + r * 72 + u * 8) = pa;
        }
        __syncthreads();
    }
#pragma unroll
    for (int nt = 0; nt < 4; nt++) {
        int col = nh * 32 + nt * 8 + 2 * tg;
        int r0 = i0 + mt2 * 16 + g, r1 = r0 + 8;
        sth2(&dst[(size_t)r0 * DD + col], c[nt][0], c[nt][1]);
        sth2(&dst[(size_t)r1 * DD + col], c[nt][2], c[nt][3]);
    }
}

// ---------------- diffusion finish ----------------
#define DF_O_W1 0
#define DF_O_W2 17408
#define DF_O_HS 34816
#define DF_O_HD 39168
#define DF_HALVES 43520
#define DF_SMEM (DF_HALVES * 2)
__global__ void __launch_bounds__(256, 2) k_dfin(
    const float* __restrict__ dw, const float* __restrict__ mw,
    const float* __restrict__ convw, const float* __restrict__ convb,
    const float* __restrict__ mbp) {
    extern __shared__ unsigned char smraw[];
    __half* ws1 = (__half*)smraw + DF_O_W1;
    __half* ws2 = (__half*)smraw + DF_O_W2;
    __half* hs = (__half*)smraw + DF_O_HS;
    __half* hd = (__half*)smraw + DF_O_HD;
    int tid = threadIdx.x, lane = tid & 31, w = tid >> 5, g = lane >> 2, tg = lane & 3;
    int row0 = blockIdx.x * 32;

    for (int e = tid; e < 4096; e += 256) {
        int r = e >> 5, k4 = (e & 31) * 4;
        float4 v = *(const float4*)(dw + (size_t)r * DD + k4);
        sth2(ws1 + r * RW + k4, v.x, v.y);
        sth2(ws1 + r * RW + k4 + 2, v.z, v.w);
        float4 v2 = *(const float4*)(mw + (size_t)r * 256 + 128 + k4);
        sth2(ws2 + r * RW + k4, v2.x, v2.y);
        sth2(ws2 + r * RW + k4 + 2, v2.z, v2.w);
    }
    float c0 = convw[0], c1 = convw[1], c2 = convw[2], cb = convb[0];
    for (int e = tid; e < 1024; e += 256) {
        int r = e >> 5, n4 = (e & 31) * 4;
        uint2 rh = *(const uint2*)(g_ret + ((size_t)(row0 + r) * TT + (TT - 1)) * DD + n4);
        uint2 ra = *(const uint2*)(g_cur_a + (size_t)(row0 + r) * DD + n4);
        uint2 rb = *(const uint2*)(g_cur_b + (size_t)(row0 + r) * DD + n4);
        const __half* hp = (const __half*)&rh;
        const __half* ap = (const __half*)&ra;
        const __half* bp = (const __half*)&rb;
        float f0 = c0 * __half2float(hp[0]) + c1 * __half2float(ap[0]) + c2 * __half2float(bp[0]);
        float f1 = c0 * __half2float(hp[1]) + c1 * __half2float(ap[1]) + c2 * __half2float(bp[1]);
        float f2 = c0 * __half2float(hp[2]) + c1 * __half2float(ap[2]) + c2 * __half2float(bp[2]);
        float f3 = c0 * __half2float(hp[3]) + c1 * __half2float(ap[3]) + c2 * __half2float(bp[3]);
        sth2(&hs[r * RW + n4], f0, f1);
        sth2(&hs[r * RW + n4 + 2], f2, f3);
    }
    __syncthreads();

    int mt2 = w & 1, nq = w >> 1;
    {
        float c[4][4];
#pragma unroll
        for (int nt = 0; nt < 4; nt++)
#pragma unroll
            for (int ci = 0; ci < 4; ci++) c[nt][ci] = 0.f;
#pragma unroll
        for (int ks2 = 0; ks2 < 8; ks2++) {
            int off = ks2 * 16;
            const __half* ar0 = hs + (mt2 * 16 + g) * RW + off + 2 * tg;
            const __half* ar1 = ar0 + 8 * RW;
            unsigned a0 = ldh2(ar0), a1 = ldh2(ar1);
            unsigned a2 = ldh2(ar0 + 8), a3 = ldh2(ar1 + 8);
#pragma unroll
            for (int nt = 0; nt < 4; nt++) {
                int nc = nq * 32 + nt * 8 + g;
                const __half* br = ws1 + nc * RW + off + 2 * tg;
                unsigned b0 = ldh2(br), b1 = ldh2(br + 8);
                MMA_F16(c[nt], a0, a1, a2, a3, b0, b1);
            }
        }
#pragma unroll
        for (int nt = 0; nt < 4; nt++) {
            int col0 = nq * 32 + nt * 8 + 2 * tg;
#pragma unroll
            for (int ci2 = 0; ci2 < 2; ci2++) {
                int r = mt2 * 16 + g + ci2 * 8;
                sth2(&hd[r * RW + col0], lrelu(c[nt][ci2 * 2] + cb),
                     lrelu(c[nt][ci2 * 2 + 1] + cb));
            }
        }
    }
    __syncthreads();
    {
        float c[4][4];
#pragma unroll
        for (int nt = 0; nt < 4; nt++)
#pragma unroll
            for (int ci = 0; ci < 4; ci++) c[nt][ci] = 0.f;
#pragma unroll
        for (int ks2 = 0; ks2 < 8; ks2++) {
            int off = ks2 * 16;
            const __half* ar0 = hd + (mt2 * 16 + g) * RW + off + 2 * tg;
            const __half* ar1 = ar0 + 8 * RW;
            unsigned a0 = ldh2(ar0), a1 = ldh2(ar1);
            unsigned a2 = ldh2(ar0 + 8), a3 = ldh2(ar1 + 8);
#pragma unroll
            for (int nt = 0; nt < 4; nt++) {
                int nc = nq * 32 + nt * 8 + g;
                const __half* br = ws2 + nc * RW + off + 2 * tg;
                unsigned b0 = ldh2(br), b1 = ldh2(br + 8);
                MMA_F16(c[nt], a0, a1, a2, a3, b0, b1);
            }
        }
#pragma unroll
        for (int nt = 0; nt < 4; nt++) {
            int col0 = nq * 32 + nt * 8 + 2 * tg;
            float m0 = mbp[col0], m1 = mbp[col0 + 1];
#pragma unroll
            for (int ci2 = 0; ci2 < 2; ci2++) {
                int r = mt2 * 16 + g + ci2 * 8;
                float2 ov = make_float2(c[nt][ci2 * 2] + m0, c[nt][ci2 * 2 + 1] + m1);
                *(float2*)&g_bias2[(size_t)(row0 + r) * DD + col0] = ov;
            }
        }
    }
}

// ---------------- MLP: cp.async double-buffered ----------------
#define MLP_O_WS 0
#define MLP_O_H0 17408
#define MLP_O_H1 26112
#define MLP_HALVES 34816
#define MLP_SMEM (MLP_HALVES * 2)
__global__ void __launch_bounds__(256) k_mlp(const float* __restrict__ mw) {
    extern __shared__ unsigned char smraw[];
    __half* ws = (__half*)smraw + MLP_O_WS;
    int tid = threadIdx.x, lane = tid & 31, w = tid >> 5, g = lane >> 2, tg = lane & 3;
    unsigned sb_base = (unsigned)__cvta_generic_to_shared(ws);
    unsigned sb_ws = sb_base;
    unsigned sb_h[2] = {sb_base + MLP_O_H0 * 2, sb_base + MLP_O_H1 * 2};
    unsigned dA = DLA(lane, RW), dB = DLB(lane, RW);

    for (int e = tid; e < 4096; e += 256) {
        int r = e >> 5, k4 = (e & 31) * 4;
        float4 v = *(const float4*)(mw + (size_t)r * 256 + k4);
        sth2(ws + r * RW + k4, v.x, v.y);
        sth2(ws + r * RW + k4 + 2, v.z, v.w);
    }

    int b0 = blockIdx.x * 8;
    {
        int r = tid >> 4, c8 = (tid & 15) * 8;
        const __half* src = g_ret + (size_t)b0 * (TT * DD);
        CP_ASYNC16(sb_h[0] + (r * RW + c8) * 2, src + r * DD + c8);
        CP_ASYNC16(sb_h[0] + ((r + 16) * RW + c8) * 2, src + (r + 16) * DD + c8);
        CP_ASYNC16(sb_h[0] + ((r + 32) * RW + c8) * 2, src + (r + 32) * DD + c8);
        CP_ASYNC16(sb_h[0] + ((r + 48) * RW + c8) * 2, src + (r + 48) * DD + c8);
    }
    CP_COMMIT();

    for (int bi = 0; bi < 8; bi++) {
        int s = b0 + bi;
        int cur = bi & 1;
        CP_WAIT0();
        __syncthreads();
        if (bi < 7) {
            int r = tid >> 4, c8 = (tid & 15) * 8;
            const __half* src = g_ret + (size_t)(s + 1) * (TT * DD);
            unsigned db = sb_h[cur ^ 1];
            CP_ASYNC16(db + (r * RW + c8) * 2, src + r * DD + c8);
            CP_ASYNC16(db + ((r + 16) * RW + c8) * 2, src + (r + 16) * DD + c8);
            CP_ASYNC16(db + ((r + 32) * RW + c8) * 2, src + (r + 32) * DD + c8);
            CP_ASYNC16(db + ((r + 48) * RW + c8) * 2, src + (r + 48) * DD + c8);
        }
        CP_COMMIT();

        float c[4][2][4];
#pragma unroll
        for (int mt = 0; mt < 4; mt++)
#pragma unroll
            for (int nt = 0; nt < 2; nt++)
#pragma unroll
                for (int ci = 0; ci < 4; ci++) c[mt][nt][ci] = 0.f;
#pragma unroll
        for (int ks2 = 0; ks2 < 8; ks2++) {
            int off = ks2 * 16;
            unsigned a[4][4];
#pragma unroll
            for (int mt = 0; mt < 4; mt++)
                ldsmx4(a[mt], sb_h[cur] + ((mt * 16) * RW + off) * 2 + dA);
#pragma unroll
            for (int nt = 0; nt < 2; nt++) {
                unsigned b0r, b1r;
                ldsmx2(b0r, b1r, sb_ws + ((w * 16 + nt * 8) * RW + off) * 2 + dB);
#pragma unroll
                for (int mt = 0; mt < 4; mt++)
                    MMA_F16(c[mt][nt], a[mt][0], a[mt][1], a[mt][2], a[mt][3], b0r, b1r);
            }
        }
        __half* gh = g_h + (size_t)s * (TT * DD);
        const float* bsrc = g_bias2 + (size_t)s * DD;
#pragma unroll
        for (int mt = 0; mt < 4; mt++)
#pragma unroll
            for (int nt = 0; nt < 2; nt++) {
                int col0 = w * 16 + nt * 8 + 2 * tg;
                float2 bv = *(const float2*)&bsrc[col0];
#pragma unroll
                for (int ci2 = 0; ci2 < 2; ci2++) {
                    int r = mt * 16 + g + ci2 * 8;
                    sth2(&gh[r * DD + col0], lrelu(c[mt][nt][ci2 * 2] + bv.x),
                         lrelu(c[mt][nt][ci2 * 2 + 1] + bv.y));
                }
            }
    }
}

// ---------------- head ----------------
__global__ void k_head(const float* __restrict__ h1w, const float* __restrict__ h1b,
                       const float* __restrict__ h2w, const float* __restrict__ h2b,
                       float* __restrict__ out) {
    __shared__ float wt[128 * 65];
    __shared__ float lr[128];
    __shared__ float red[2];
    int bn = blockIdx.x;
    int tid = threadIdx.x;
    for (int e = tid; e < 128; e += 64)
        lr[e] = __half2float(g_h[((size_t)bn * TT + (TT - 1)) * DD + e]);
    for (int e = tid; e < 64 * 128; e += 64) {
        int jj = e >> 7, k = e & 127;
        wt[k * 65 + jj] = h1w[e];
    }
    __syncthreads();
    float s = 0.f;
    for (int k = 0; k < 128; k++) s += lr[k] * wt[k * 65 + tid];
    s += h1b[tid];
    s = lrelu(s);
    s *= h2w[tid];
#pragma unroll
    for (int o = 16; o; o >>= 1) s += __shfl_down_sync(0xffffffffu, s, o);
    if ((tid & 31) == 0) red[tid >> 5] = s;
    __syncthreads();
    if (tid == 0) out[bn] = red[0] + red[1] + h2b[0];
}

// ---------------- launch ----------------
extern "C" void kernel_launch(void* const* d_in, const int* in_sizes, int n_in,
                              void* d_out, int out_size) {
    const float* x      = (const float*)d_in[0];
    const float* adj    = (const float*)d_in[1];
    const float* proj_w = (const float*)d_in[2];
    const float* proj_b = (const float*)d_in[3];
    const float* pos    = (const float*)d_in[4];
    const float* diff_w = (const float*)d_in[5];
    const float* conv_w = (const float*)d_in[6];
    const float* conv_b = (const float*)d_in[7];
    const float* wq_w   = (const float*)d_in[8];
    const float* wq_b   = (const float*)d_in[9];
    const float* wk_w   = (const float*)d_in[10];
    const float* wk_b   = (const float*)d_in[11];
    const float* wv_w   = (const float*)d_in[12];
    const float* wv_b   = (const float*)d_in[13];
    const float* gn_w   = (const float*)d_in[14];
    const float* gn_b   = (const float*)d_in[15];
    const float* gamma  = (const float*)d_in[16];
    const float* ln_w   = (const float*)d_in[17];
    const float* ln_b   = (const float*)d_in[18];
    const float* mlp_w  = (const float*)d_in[19];
    const float* mlp_b  = (const float*)d_in[20];
    const float* h1w    = (const float*)d_in[21];
    const float* h1b    = (const float*)d_in[22];
    const float* h2w    = (const float*)d_in[23];
    const float* h2b    = (const float*)d_in[24];

    cudaFuncSetAttribute(k_ret, cudaFuncAttributeMaxDynamicSharedMemorySize, RET_SMEM);
    cudaFuncSetAttribute(k_mlp, cudaFuncAttributeMaxDynamicSharedMemorySize, MLP_SMEM);
    cudaFuncSetAttribute(k_dfin, cudaFuncAttributeMaxDynamicSharedMemorySize, DF_SMEM);

    k_x16<<<BN, 128>>>(x);
    k_adjn<<<BB * NN, 256>>>(adj);
    k_a2<<<dim3(NN / 64, NN / 64, BB), 256>>>();

    for (int l = 0; l < 2; l++) {
        k_ret<<<NSM, 512, RET_SMEM>>>(
            wq_w + l * DD * DD, wq_b + l * DD, wk_w + l * DD * DD, wk_b + l * DD,
            wv_w + l * DD * DD, wv_b + l * DD, gn_w + l * DD, gn_b + l * DD,
            gamma + l, ln_w + l * DD, ln_b + l * DD,
            proj_w, proj_b, pos, l == 0 ? 1 : 0);
        k_hopP<<<dim3(NN / 32, BB, 2), 256>>>();
        k_dfin<<<BN / 32, 256, DF_SMEM>>>(diff_w + l * DD * DD,
                                          mlp_w + (size_t)l * DD * 2 * DD,
                                          conv_w + l * 3, conv_b + l, mlp_b + l * DD);
        k_mlp<<<BN / 8, 256, MLP_SMEM>>>(mlp_w + (size_t)l * DD * 2 * DD);
    }
    k_head<<<BN, 64>>>(h1w, h1b, h2w, h2b, (float*)d_out);
}

// round 17
// speedup vs baseline: 1.0637x; 1.0637x over previous
#include <cuda_runtime.h>
#include <cuda_fp16.h>
#include <math.h>

#define BB 4
#define NN 512
#define BN 2048
#define TT 64
#define DD 128
#define HH 4
#define HD 32
#define EPS 1e-5f
#define LSLOPE 0.2f
#define NSM 148

__device__ __half g_h[BN * TT * DD];
__device__ __half g_ret[BN * TT * DD];
__device__ __half g_x16[BN * TT * 16];
__device__ __half g_adjn[BB * NN * NN];
__device__ __half g_adj2[BB * NN * NN];
__device__ __half g_hlT[BB * DD * NN];
__device__ __half g_cur_a[BB * NN * DD];
__device__ __half g_cur_b[BB * NN * DD];
__device__ __half g_lastH[BN * DD];
__device__ float g_bias2[BN * DD];

__device__ __forceinline__ float lrelu(float v) { return v > 0.f ? v : LSLOPE * v; }
__device__ __forceinline__ unsigned ldh2(const __half* p) { return *(const unsigned*)p; }
__device__ __forceinline__ void sth2(__half* p, float a, float b) {
    *(__half2*)p = __floats2half2_rn(a, b);
}

#define MMA_F16(C, A0, A1, A2, A3, B0, B1)                                              \
    asm volatile(                                                                       \
        "mma.sync.aligned.m16n8k16.row.col.f32.f16.f16.f32 "                            \
        "{%0,%1,%2,%3},{%4,%5,%6,%7},{%8,%9},{%0,%1,%2,%3};"                            \
        : "+f"((C)[0]), "+f"((C)[1]), "+f"((C)[2]), "+f"((C)[3])                        \
        : "r"(A0), "r"(A1), "r"(A2), "r"(A3), "r"(B0), "r"(B1))

__device__ __forceinline__ void ldsmx4(unsigned r[4], unsigned addr) {
    asm volatile("ldmatrix.sync.aligned.m8n8.x4.shared.b16 {%0,%1,%2,%3}, [%4];"
                 : "=r"(r[0]), "=r"(r[1]), "=r"(r[2]), "=r"(r[3]) : "r"(addr));
}
__device__ __forceinline__ void ldsmx4t(unsigned r[4], unsigned addr) {
    asm volatile("ldmatrix.sync.aligned.m8n8.x4.trans.shared.b16 {%0,%1,%2,%3}, [%4];"
                 : "=r"(r[0]), "=r"(r[1]), "=r"(r[2]), "=r"(r[3]) : "r"(addr));
}
__device__ __forceinline__ void ldsmx2(unsigned& r0, unsigned& r1, unsigned addr) {
    asm volatile("ldmatrix.sync.aligned.m8n8.x2.shared.b16 {%0,%1}, [%2];"
                 : "=r"(r0), "=r"(r1) : "r"(addr));
}
#define CP_ASYNC16(dst, src)                                                            \
    asm volatile("cp.async.cg.shared.global [%0], [%1], 16;" ::"r"(dst), "l"(src))
#define CP_COMMIT() asm volatile("cp.async.commit_group;")
#define CP_WAIT0() asm volatile("cp.async.wait_group 0;")

#define RW 136
#define QBW 392

#define DLA(lane, S) ((((lane) & 15) * (S) + ((lane) >> 4) * 8) * 2)
#define DLB(lane, S) ((((lane) & 7) * (S) + (((lane) >> 3) & 1) * 8) * 2)

// ---------------- x -> fp16 padded [64][16] ----------------
__global__ void k_x16(const float* __restrict__ x) {
    int bn = blockIdx.x;
    int tid = threadIdx.x;
    const float* xb = x + (size_t)bn * TT * 8;
    __half* ob = g_x16 + (size_t)bn * TT * 16;
    for (int e = tid; e < 1024; e += 128) {
        int t = e >> 4, f = e & 15;
        ob[e] = (f < 8) ? __float2half(xb[t * 8 + f]) : __half(0);
    }
}

// ---------------- adj row-normalize ----------------
__global__ void k_adjn(const float* __restrict__ adj) {
    int row = blockIdx.x;
    __shared__ float red[8];
    const float* ar = adj + (size_t)row * NN;
    float s = 0.f;
    for (int j = threadIdx.x; j < NN; j += 256) s += ar[j];
#pragma unroll
    for (int o = 16; o; o >>= 1) s += __shfl_down_sync(0xffffffffu, s, o);
    if ((threadIdx.x & 31) == 0) red[threadIdx.x >> 5] = s;
    __syncthreads();
    if (threadIdx.x == 0) {
        float t = 0.f;
#pragma unroll
        for (int w = 0; w < 8; w++) t += red[w];
        red[0] = 1.0f / (t + 1e-9f);
    }
    __syncthreads();
    float inv = red[0];
    for (int j = threadIdx.x; j < NN; j += 256)
        g_adjn[(size_t)row * NN + j] = __float2half(ar[j] * inv);
}

// ---------------- A2 = A@A ----------------
__global__ void __launch_bounds__(256, 4) k_a2() {
    __shared__ __half As[64 * 72];
    __shared__ __half Bs[64 * 72];
    int tid = threadIdx.x, lane = tid & 31, w = tid >> 5, g = lane >> 2, tg = lane & 3;
    int m0 = blockIdx.x * 64, n0 = blockIdx.y * 64, b = blockIdx.z;
    const __half* adjb = g_adjn + (size_t)b * NN * NN;
    int mt = w & 3, nh = w >> 2;

    float c[4][4];
#pragma unroll
    for (int nt = 0; nt < 4; nt++)
#pragma unroll
        for (int ci = 0; ci < 4; ci++) c[nt][ci] = 0.f;

    for (int kc = 0; kc < 8; kc++) {
        __syncthreads();
        for (int e = tid; e < 512; e += 256) {
            int r = e >> 3, u = e & 7;
            *(uint4*)(As + r * 72 + u * 8) =
                *(const uint4*)(adjb + (size_t)(m0 + r) * NN + kc * 64 + u * 8);
        }
        for (int e = tid; e < 512; e += 256) {
            int kr = e >> 3, u = e & 7;
            uint4 raw = *(const uint4*)(adjb + (size_t)(kc * 64 + kr) * NN + n0 + u * 8);
            const __half* hp = (const __half*)&raw;
#pragma unroll
            for (int j = 0; j < 8; j++) Bs[(u * 8 + j) * 72 + kr] = hp[j];
        }
        __syncthreads();
#pragma unroll
        for (int ks2 = 0; ks2 < 4; ks2++) {
            int off = ks2 * 16;
            const __half* ar0 = As + (mt * 16 + g) * 72 + off + 2 * tg;
            const __half* ar1 = ar0 + 8 * 72;
            unsigned a0 = ldh2(ar0), a1 = ldh2(ar1);
            unsigned a2 = ldh2(ar0 + 8), a3 = ldh2(ar1 + 8);
#pragma unroll
            for (int nt = 0; nt < 4; nt++) {
                const __half* br = Bs + (nh * 32 + nt * 8 + g) * 72 + off + 2 * tg;
                unsigned b0 = ldh2(br), b1 = ldh2(br + 8);
                MMA_F16(c[nt], a0, a1, a2, a3, b0, b1);
            }
        }
    }
    __half* out = g_adj2 + (size_t)b * NN * NN;
#pragma unroll
    for (int nt = 0; nt < 4; nt++) {
        int col = n0 + nh * 32 + nt * 8 + 2 * tg;
        int r0 = m0 + mt * 16 + g, r1 = r0 + 8;
        sth2(&out[(size_t)r0 * NN + col], c[nt][0], c[nt][1]);
        sth2(&out[(size_t)r1 * NN + col], c[nt][2], c[nt][3]);
    }
}

// ---------------- fused retention (lay0 factored QKV; last-layer store skip) ----------------
#define O_HB0 0
#define O_HB1 8704
#define O_QS 17408
#define O_KS 26112
#define O_VS 34816
#define O_BC 43520
#define O_QB 52736
#define RET_HALVES 77824
#define RET_SMEM (RET_HALVES * 2)

__global__ void __launch_bounds__(512, 1) k_ret(
    const float* __restrict__ wq, const float* __restrict__ bq,
    const float* __restrict__ wk, const float* __restrict__ bk,
    const float* __restrict__ wv, const float* __restrict__ bv,
    const float* __restrict__ gnw, const float* __restrict__ gnb,
    const float* __restrict__ gam,
    const float* __restrict__ lnw, const float* __restrict__ lnb,
    const float* __restrict__ pw, const float* __restrict__ pb,
    const float* __restrict__ pos, int lay0, int last) {
    extern __shared__ unsigned char smraw[];
    __half* smh = (__half*)smraw;
    __half* ws = smh;
    __half* Qs = smh + O_QS;
    __half* Ks = smh + O_KS;
    __half* Vs = smh + O_VS;
    __half* BcS = smh + O_BC;
    __half* QbS = smh + O_QB;
    __shared__ float cbias[384];
    __shared__ float gpow[64];
    __shared__ float shead[8];
    __shared__ float sum1[64], sum2[64];
    __shared__ float sgw[128], sgb[128], slw[128], slb[128];
    __shared__ float pwsm[128 * 8];

    int tid = threadIdx.x, lane = tid & 31, w = tid >> 5, g = lane >> 2, tg = lane & 3;

    unsigned sb_base = (unsigned)__cvta_generic_to_shared(smh);
    unsigned sb_hb[2] = {sb_base + O_HB0 * 2, sb_base + O_HB1 * 2};
    unsigned sb_qs = sb_base + O_QS * 2;
    unsigned sb_ks = sb_base + O_KS * 2;
    unsigned sb_vs = sb_base + O_VS * 2;
    unsigned dA_RW = DLA(lane, RW), dB_RW = DLB(lane, RW);
    unsigned dA24 = DLA(lane, 24), dB24 = DLB(lane, 24);

    for (int e = tid; e < 12288; e += 512) {
        int r = e >> 5, k4 = (e & 31) * 4;
        const float* src = (r < 128) ? (wq + r * DD)
                         : (r < 256) ? (wk + (r - 128) * DD)
                                     : (wv + (r - 256) * DD);
        float4 v = *(const float4*)(src + k4);
        __half* dst = ws + r * RW + k4;
        sth2(dst, v.x, v.y);
        sth2(dst + 2, v.z, v.w);
    }
    for (int e = tid; e < 384; e += 512)
        cbias[e] = e < 128 ? bq[e] : (e < 256 ? bk[e - 128] : bv[e - 256]);
    if (tid < 64) gpow[tid] = powf(gam[0], (float)tid);
    if (tid < 128) {
        sgw[tid] = gnw[tid];
        sgb[tid] = gnb[tid];
        slw[tid] = lnw[tid];
        slb[tid] = lnb[tid];
    }
    unsigned Breg[8][3][2];

    if (lay0) {
        for (int e = tid; e < 1024; e += 512) pwsm[e] = pw[e];
        for (int e = tid; e < 4096; e += 512) {
            int t = e >> 6, d2 = (e & 63) * 2;
            float a = pos[t * DD + d2] + pb[d2];
            float b = pos[t * DD + d2 + 1] + pb[d2 + 1];
            sth2(&QbS[t * RW + d2], a, b);
        }
        __syncthreads();
        float qc[4][3][4];
#pragma unroll
        for (int m2 = 0; m2 < 4; m2++)
#pragma unroll
            for (int nt = 0; nt < 3; nt++)
#pragma unroll
                for (int ci = 0; ci < 4; ci++) qc[m2][nt][ci] = 0.f;
#pragma unroll
        for (int ks2 = 0; ks2 < 8; ks2++) {
            int off = ks2 * 16;
            unsigned a[4][4];
#pragma unroll
            for (int m2 = 0; m2 < 4; m2++)
                ldsmx4(a[m2], sb_base + (O_QB + (m2 * 16) * RW + off) * 2 + dA_RW);
#pragma unroll
            for (int nt = 0; nt < 3; nt++) {
                unsigned b0, b1;
                ldsmx2(b0, b1, sb_base + ((w * 24 + nt * 8) * RW + off) * 2 + dB_RW);
#pragma unroll
                for (int m2 = 0; m2 < 4; m2++)
                    MMA_F16(qc[m2][nt], a[m2][0], a[m2][1], a[m2][2], a[m2][3], b0, b1);
            }
        }
        float pacc[8];
#pragma unroll
        for (int f = 0; f < 8; f++) pacc[f] = 0.f;
        if (tid < 384) {
            for (int d = 0; d < 128; d++) {
                float wv2 = __half2float(ws[tid * RW + d]);
                float4 p0 = *(float4*)&pwsm[d * 8];
                float4 p1 = *(float4*)&pwsm[d * 8 + 4];
                pacc[0] += wv2 * p0.x; pacc[1] += wv2 * p0.y;
                pacc[2] += wv2 * p0.z; pacc[3] += wv2 * p0.w;
                pacc[4] += wv2 * p1.x; pacc[5] += wv2 * p1.y;
                pacc[6] += wv2 * p1.z; pacc[7] += wv2 * p1.w;
            }
        }
        __syncthreads();
        if (tid < 384) {
#pragma unroll
            for (int f = 0; f < 8; f++) BcS[tid * 24 + f] = __float2half(pacc[f]);
#pragma unroll
            for (int f = 8; f < 16; f++) BcS[tid * 24 + f] = __half(0);
        }
#pragma unroll
        for (int m2 = 0; m2 < 4; m2++) {
            int r0e = m2 * 16 + g, r1e = r0e + 8;
#pragma unroll
            for (int nt = 0; nt < 3; nt++) {
                int gc0 = w * 24 + nt * 8 + 2 * tg;
                sth2(&QbS[r0e * QBW + gc0], qc[m2][nt][0] + cbias[gc0],
                     qc[m2][nt][1] + cbias[gc0 + 1]);
                sth2(&QbS[r1e * QBW + gc0], qc[m2][nt][2] + cbias[gc0],
                     qc[m2][nt][3] + cbias[gc0 + 1]);
            }
        }
        __syncthreads();
        ldsmx2(Breg[0][0][0], Breg[0][0][1], sb_base + (O_BC + (w * 24 + 0) * 24) * 2 + dB24);
        ldsmx2(Breg[0][1][0], Breg[0][1][1], sb_base + (O_BC + (w * 24 + 8) * 24) * 2 + dB24);
        ldsmx2(Breg[0][2][0], Breg[0][2][1], sb_base + (O_BC + (w * 24 + 16) * 24) * 2 + dB24);
    } else {
        __syncthreads();
#pragma unroll
        for (int ks2 = 0; ks2 < 8; ks2++)
#pragma unroll
            for (int nt = 0; nt < 3; nt++)
                ldsmx2(Breg[ks2][nt][0], Breg[ks2][nt][1],
                       sb_base + ((w * 24 + nt * 8) * RW + ks2 * 16) * 2 + dB_RW);
        __syncthreads();
    }

    int hh = w >> 2, mt = w & 3;
    int bid = blockIdx.x;
    int s0 = (int)(((long)bid * BN) / NSM);
    int s1 = (int)(((long)bid + 1) * BN / NSM);

    if (lay0) {
        if (tid < 128) {
            int r = tid >> 1, hc = (tid & 1) * 8;
            CP_ASYNC16(sb_hb[0] + (r * 24 + hc) * 2, g_x16 + (size_t)s0 * 1024 + r * 16 + hc);
        }
    } else {
        int r = tid >> 4, c8 = (tid & 15) * 8;
        const __half* src = g_h + (size_t)s0 * (TT * DD);
        CP_ASYNC16(sb_hb[0] + (r * RW + c8) * 2, src + r * DD + c8);
        CP_ASYNC16(sb_hb[0] + ((r + 32) * RW + c8) * 2, src + (r + 32) * DD + c8);
    }
    CP_COMMIT();

    for (int s = s0; s < s1; s++) {
        int cur = (s - s0) & 1;
        CP_WAIT0();
        __syncthreads();  // [B1]
        if (tid < 64) { sum1[tid] = 0.f; sum2[tid] = 0.f; }
        if (tid < 8) shead[tid] = 0.f;
        if (s + 1 < s1) {
            unsigned db = sb_hb[cur ^ 1];
            if (lay0) {
                if (tid < 128) {
                    int r = tid >> 1, hc = (tid & 1) * 8;
                    CP_ASYNC16(db + (r * 24 + hc) * 2,
                               g_x16 + (size_t)(s + 1) * 1024 + r * 16 + hc);
                }
            } else {
                int r = tid >> 4, c8 = (tid & 15) * 8;
                const __half* src = g_h + (size_t)(s + 1) * (TT * DD);
                CP_ASYNC16(db + (r * RW + c8) * 2, src + r * DD + c8);
                CP_ASYNC16(db + ((r + 32) * RW + c8) * 2, src + (r + 32) * DD + c8);
            }
        }
        CP_COMMIT();

        // ---- QKV
        float c[4][3][4];
#pragma unroll
        for (int m2 = 0; m2 < 4; m2++)
#pragma unroll
            for (int nt = 0; nt < 3; nt++)
#pragma unroll
                for (int ci = 0; ci < 4; ci++) c[m2][nt][ci] = 0.f;
        if (lay0) {
            unsigned a[4][4];
#pragma unroll
            for (int m2 = 0; m2 < 4; m2++)
                ldsmx4(a[m2], sb_hb[cur] + ((m2 * 16) * 24) * 2 + dA24);
#pragma unroll
            for (int m2 = 0; m2 < 4; m2++)
#pragma unroll
                for (int nt = 0; nt < 3; nt++)
                    MMA_F16(c[m2][nt], a[m2][0], a[m2][1], a[m2][2], a[m2][3],
                            Breg[0][nt][0], Breg[0][nt][1]);
        } else {
#pragma unroll
            for (int ks2 = 0; ks2 < 8; ks2++) {
                int off = ks2 * 16;
                unsigned a[4][4];
#pragma unroll
                for (int m2 = 0; m2 < 4; m2++)
                    ldsmx4(a[m2], sb_hb[cur] + ((m2 * 16) * RW + off) * 2 + dA_RW);
#pragma unroll
                for (int m2 = 0; m2 < 4; m2++)
#pragma unroll
                    for (int nt = 0; nt < 3; nt++)
                        MMA_F16(c[m2][nt], a[m2][0], a[m2][1], a[m2][2], a[m2][3],
                                Breg[ks2][nt][0], Breg[ks2][nt][1]);
            }
        }

#pragma unroll
        for (int m2 = 0; m2 < 4; m2++) {
            int r0e = m2 * 16 + g, r1e = r0e + 8;
#pragma unroll
            for (int nt = 0; nt < 3; nt++) {
                int gc0 = w * 24 + nt * 8 + 2 * tg;
                float b00, b01, b10, b11;
                if (lay0) {
                    unsigned p0 = ldh2(&QbS[r0e * QBW + gc0]);
                    unsigned p1 = ldh2(&QbS[r1e * QBW + gc0]);
                    __half2 h0 = *(__half2*)&p0, h1 = *(__half2*)&p1;
                    b00 = __low2float(h0); b01 = __high2float(h0);
                    b10 = __low2float(h1); b11 = __high2float(h1);
                } else {
                    b00 = b10 = cbias[gc0];
                    b01 = b11 = cbias[gc0 + 1];
                }
                float v00 = c[m2][nt][0] + b00, v01 = c[m2][nt][1] + b01;
                float v10 = c[m2][nt][2] + b10, v11 = c[m2][nt][3] + b11;
                if (gc0 < 128) {
                    sth2(&Qs[r0e * RW + gc0], v00, v01);
                    sth2(&Qs[r1e * RW + gc0], v10, v11);
                } else if (gc0 < 256) {
                    int k0 = gc0 - 128;
                    sth2(&Ks[r0e * RW + k0], v00, v01);
                    sth2(&Ks[r1e * RW + k0], v10, v11);
                } else {
                    int d0 = gc0 - 256;
                    sth2(&Vs[r0e * RW + d0], v00, v01);
                    sth2(&Vs[r1e * RW + d0], v10, v11);
                }
            }
        }
        __syncthreads();  // [B2]

        // ---- S = Q K^T
        unsigned qa[2][4];
        ldsmx4(qa[0], sb_qs + ((mt * 16) * RW + hh * 32) * 2 + dA_RW);
        ldsmx4(qa[1], sb_qs + ((mt * 16) * RW + hh * 32 + 16) * 2 + dA_RW);
        float scC[8][4];
#pragma unroll
        for (int nt = 0; nt < 8; nt++)
#pragma unroll
            for (int ci = 0; ci < 4; ci++) scC[nt][ci] = 0.f;
#pragma unroll
        for (int ks2 = 0; ks2 < 2; ks2++) {
            int off = hh * 32 + ks2 * 16;
#pragma unroll
            for (int np = 0; np < 4; np++) {
                unsigned bb[4];
                ldsmx4(bb, sb_ks + ((np * 16) * RW + off) * 2 + dA_RW);
                MMA_F16(scC[np * 2], qa[ks2][0], qa[ks2][1], qa[ks2][2], qa[ks2][3],
                        bb[0], bb[2]);
                MMA_F16(scC[np * 2 + 1], qa[ks2][0], qa[ks2][1], qa[ks2][2], qa[ks2][3],
                        bb[1], bb[3]);
            }
        }
        unsigned sa[4][4];
        {
            int q0 = mt * 16 + g, q1 = q0 + 8;
#pragma unroll
            for (int j = 0; j < 4; j++) {
                int k0 = (2 * j) * 8 + 2 * tg;
                int k1 = k0 + 8;
                float v00 = (k0 <= q0) ? scC[2 * j][0] * gpow[q0 - k0] : 0.f;
                float v01 = (k0 + 1 <= q0) ? scC[2 * j][1] * gpow[q0 - k0 - 1] : 0.f;
                float v10 = (k0 <= q1) ? scC[2 * j][2] * gpow[q1 - k0] : 0.f;
                float v11 = (k0 + 1 <= q1) ? scC[2 * j][3] * gpow[q1 - k0 - 1] : 0.f;
                float u00 = (k1 <= q0) ? scC[2 * j + 1][0] * gpow[q0 - k1] : 0.f;
                float u01 = (k1 + 1 <= q0) ? scC[2 * j + 1][1] * gpow[q0 - k1 - 1] : 0.f;
                float u10 = (k1 <= q1) ? scC[2 * j + 1][2] * gpow[q1 - k1] : 0.f;
                float u11 = (k1 + 1 <= q1) ? scC[2 * j + 1][3] * gpow[q1 - k1 - 1] : 0.f;
                __half2 t0 = __floats2half2_rn(v00, v01);
                __half2 t1 = __floats2half2_rn(v10, v11);
                __half2 t2 = __floats2half2_rn(u00, u01);
                __half2 t3 = __floats2half2_rn(u10, u11);
                sa[j][0] = *(unsigned*)&t0;
                sa[j][1] = *(unsigned*)&t1;
                sa[j][2] = *(unsigned*)&t2;
                sa[j][3] = *(unsigned*)&t3;
            }
        }

        // ---- O = S V
        float oc[4][4];
#pragma unroll
        for (int nt = 0; nt < 4; nt++)
#pragma unroll
            for (int ci = 0; ci < 4; ci++) oc[nt][ci] = 0.f;
#pragma unroll
        for (int j = 0; j < 4; j++) {
#pragma unroll
            for (int np = 0; np < 2; np++) {
                unsigned bb[4];
                ldsmx4t(bb, sb_vs + ((j * 16) * RW + hh * 32 + np * 16) * 2 + dA_RW);
                MMA_F16(oc[np * 2], sa[j][0], sa[j][1], sa[j][2], sa[j][3], bb[0], bb[1]);
                MMA_F16(oc[np * 2 + 1], sa[j][0], sa[j][1], sa[j][2], sa[j][3], bb[2], bb[3]);
            }
        }
        {
            float s1v = 0.f, s2v = 0.f;
#pragma unroll
            for (int nt = 0; nt < 4; nt++)
#pragma unroll
                for (int ci = 0; ci < 4; ci++) {
                    float v = oc[nt][ci];
                    s1v += v; s2v += v * v;
                }
#pragma unroll
            for (int o = 16; o; o >>= 1) {
                s1v += __shfl_xor_sync(0xffffffffu, s1v, o);
                s2v += __shfl_xor_sync(0xffffffffu, s2v, o);
            }
            if (lane == 0) {
                atomicAdd(&shead[hh * 2], s1v);
                atomicAdd(&shead[hh * 2 + 1], s2v);
            }
        }
        __syncthreads();  // [B3]

        float mn, rs;
        {
            mn = shead[hh * 2] * (1.0f / 2048.0f);
            float var = shead[hh * 2 + 1] * (1.0f / 2048.0f) - mn * mn;
            rs = rsqrtf(var + EPS);
        }
        float p1[2] = {0.f, 0.f}, p2[2] = {0.f, 0.f};
#pragma unroll
        for (int nt = 0; nt < 4; nt++)
#pragma unroll
            for (int ci = 0; ci < 4; ci++) {
                int col = hh * 32 + nt * 8 + 2 * tg + (ci & 1);
                float v = (oc[nt][ci] - mn) * rs * sgw[col] + sgb[col];
                oc[nt][ci] = v;
                int hf = (ci >= 2) ? 1 : 0;
                p1[hf] += v;
                p2[hf] += v * v;
            }
#pragma unroll
        for (int o = 1; o <= 2; o <<= 1) {
            p1[0] += __shfl_xor_sync(0xffffffffu, p1[0], o);
            p1[1] += __shfl_xor_sync(0xffffffffu, p1[1], o);
            p2[0] += __shfl_xor_sync(0xffffffffu, p2[0], o);
            p2[1] += __shfl_xor_sync(0xffffffffu, p2[1], o);
        }
        int r0 = mt * 16 + g, r1 = r0 + 8;
        if (tg == 0) {
            atomicAdd(&sum1[r0], p1[0]);
            atomicAdd(&sum2[r0], p2[0]);
            atomicAdd(&sum1[r1], p1[1]);
            atomicAdd(&sum2[r1], p2[1]);
        }
        __syncthreads();  // [B4]

        float mu0 = sum1[r0] * (1.0f / 128.0f);
        float rs0 = rsqrtf(sum2[r0] * (1.0f / 128.0f) - mu0 * mu0 + EPS);
        float mu1 = sum1[r1] * (1.0f / 128.0f);
        float rs1 = rsqrtf(sum2[r1] * (1.0f / 128.0f) - mu1 * mu1 + EPS);

        __half* go = g_ret + (size_t)s * (TT * DD);
        int bb2 = s >> 9, ii = s & 511;
#pragma unroll
        for (int nt = 0; nt < 4; nt++) {
            int cb = hh * 32 + nt * 8 + 2 * tg;
            float lw0 = slw[cb], lb0 = slb[cb];
            float lw1 = slw[cb + 1], lb1 = slb[cb + 1];
            float u0 = (oc[nt][0] - mu0) * rs0 * lw0 + lb0;
            float u1 = (oc[nt][1] - mu0) * rs0 * lw1 + lb1;
            float w1x = (oc[nt][2] - mu1) * rs1 * lw0 + lb0;
            float w1y = (oc[nt][3] - mu1) * rs1 * lw1 + lb1;
            if (!last) {
                sth2(&go[r0 * DD + cb], u0, u1);
                sth2(&go[r1 * DD + cb], w1x, w1y);
            } else if (r1 == 63) {
                sth2(&go[r1 * DD + cb], w1x, w1y);
            }
            if (r1 == 63) {
                g_hlT[((size_t)bb2 * DD + cb) * NN + ii] = __float2half(w1x);
                g_hlT[((size_t)bb2 * DD + cb + 1) * NN + ii] = __float2half(w1y);
            }
        }
    }
}

// ---------------- both diffusion hops via A2 (ldmatrix) ----------------
__global__ void __launch_bounds__(256, 2) k_hopP() {
    __shared__ __half Xs[2][128 * 72];
    __shared__ __half As[2][32 * 72];
    int tid = threadIdx.x, lane = tid & 31, w = tid >> 5;
    int g = lane >> 2, tg = lane & 3;
    int i0 = blockIdx.x * 32, b = blockIdx.y, which = blockIdx.z;
    const __half* M = (which ? g_adj2 : g_adjn) + (size_t)b * NN * NN;
    const __half* Xt = g_hlT + (size_t)b * DD * NN;
    __half* dst = (which ? g_cur_b : g_cur_a) + (size_t)b * NN * DD;

    unsigned sb_xs[2] = {(unsigned)__cvta_generic_to_shared(Xs[0]),
                         (unsigned)__cvta_generic_to_shared(Xs[1])};
    unsigned sb_as[2] = {(unsigned)__cvta_generic_to_shared(As[0]),
                         (unsigned)__cvta_generic_to_shared(As[1])};
    unsigned dA72 = DLA(lane, 72);

    int mt2 = w & 1, nh = w >> 1;
    float c[4][4];
#pragma unroll
    for (int nt = 0; nt < 4; nt++)
#pragma unroll
        for (int ci = 0; ci < 4; ci++) c[nt][ci] = 0.f;

#pragma unroll
    for (int i = 0; i < 4; i++) {
        int e = tid + i * 256;
        int r = e >> 3, u = e & 7;
        *(uint4*)(Xs[0] + r * 72 + u * 8) = *(const uint4*)(Xt + (size_t)r * NN + u * 8);
    }
    {
        int r = tid >> 3, u = tid & 7;
        *(uint4*)(As[0] + r * 72 + u * 8) =
            *(const uint4*)(M + (size_t)(i0 + r) * NN + u * 8);
    }
    __syncthreads();

#pragma unroll 1
    for (int kc = 0; kc < 8; kc++) {
        uint4 px[4], pa;
        if (kc < 7) {
            int k0 = (kc + 1) * 64;
#pragma unroll
            for (int i = 0; i < 4; i++) {
                int e = tid + i * 256;
                int r = e >> 3, u = e & 7;
                px[i] = *(const uint4*)(Xt + (size_t)r * NN + k0 + u * 8);
            }
            int r = tid >> 3, u = tid & 7;
            pa = *(const uint4*)(M + (size_t)(i0 + r) * NN + k0 + u * 8);
        }
        unsigned xb = sb_xs[kc & 1];
        unsigned ab = sb_as[kc & 1];
#pragma unroll
        for (int ks2 = 0; ks2 < 4; ks2++) {
            int off = ks2 * 16;
            unsigned a[4];
            ldsmx4(a, ab + ((mt2 * 16) * 72 + off) * 2 + dA72);
#pragma unroll
            for (int np = 0; np < 2; np++) {
                unsigned bb[4];
                ldsmx4(bb, xb + ((nh * 32 + np * 16) * 72 + off) * 2 + dA72);
                MMA_F16(c[np * 2], a[0], a[1], a[2], a[3], bb[0], bb[2]);
                MMA_F16(c[np * 2 + 1], a[0], a[1], a[2], a[3], bb[1], bb[3]);
            }
        }
        if (kc < 7) {
            __half* Xn = Xs[(kc + 1) & 1];
            __half* An = As[(kc + 1) & 1];
#pragma unroll
            for (int i = 0; i < 4; i++) {
                int e = tid + i * 256;
                int r = e >> 3, u = e & 7;
                *(uint4*)(Xn + r * 72 + u * 8) = px[i];
            }
            int r = tid >> 3, u = tid & 7;
            *(uint4*)(An + r * 72 + u * 8) = pa;
        }
        __syncthreads();
    }
#pragma unroll
    for (int nt = 0; nt < 4; nt++) {
        int col = nh * 32 + nt * 8 + 2 * tg;
        int r0 = i0 + mt2 * 16 + g, r1 = r0 + 8;
        sth2(&dst[(size_t)r0 * DD + col], c[nt][0], c[nt][1]);
        sth2(&dst[(size_t)r1 * DD + col], c[nt][2], c[nt][3]);
    }
}

// ---------------- diffusion finish ----------------
#define DF_O_W1 0
#define DF_O_W2 17408
#define DF_O_HS 34816
#define DF_O_HD 39168
#define DF_HALVES 43520
#define DF_SMEM (DF_HALVES * 2)
__global__ void __launch_bounds__(256, 2) k_dfin(
    const float* __restrict__ dw, const float* __restrict__ mw,
    const float* __restrict__ convw, const float* __restrict__ convb,
    const float* __restrict__ mbp) {
    extern __shared__ unsigned char smraw[];
    __half* ws1 = (__half*)smraw + DF_O_W1;
    __half* ws2 = (__half*)smraw + DF_O_W2;
    __half* hs = (__half*)smraw + DF_O_HS;
    __half* hd = (__half*)smraw + DF_O_HD;
    int tid = threadIdx.x, lane = tid & 31, w = tid >> 5, g = lane >> 2, tg = lane & 3;
    int row0 = blockIdx.x * 32;

    for (int e = tid; e < 4096; e += 256) {
        int r = e >> 5, k4 = (e & 31) * 4;
        float4 v = *(const float4*)(dw + (size_t)r * DD + k4);
        sth2(ws1 + r * RW + k4, v.x, v.y);
        sth2(ws1 + r * RW + k4 + 2, v.z, v.w);
        float4 v2 = *(const float4*)(mw + (size_t)r * 256 + 128 + k4);
        sth2(ws2 + r * RW + k4, v2.x, v2.y);
        sth2(ws2 + r * RW + k4 + 2, v2.z, v2.w);
    }
    float c0 = convw[0], c1 = convw[1], c2 = convw[2], cb = convb[0];
    for (int e = tid; e < 1024; e += 256) {
        int r = e >> 5, n4 = (e & 31) * 4;
        uint2 rh = *(const uint2*)(g_ret + ((size_t)(row0 + r) * TT + (TT - 1)) * DD + n4);
        uint2 ra = *(const uint2*)(g_cur_a + (size_t)(row0 + r) * DD + n4);
        uint2 rb = *(const uint2*)(g_cur_b + (size_t)(row0 + r) * DD + n4);
        const __half* hp = (const __half*)&rh;
        const __half* ap = (const __half*)&ra;
        const __half* bp = (const __half*)&rb;
        float f0 = c0 * __half2float(hp[0]) + c1 * __half2float(ap[0]) + c2 * __half2float(bp[0]);
        float f1 = c0 * __half2float(hp[1]) + c1 * __half2float(ap[1]) + c2 * __half2float(bp[1]);
        float f2 = c0 * __half2float(hp[2]) + c1 * __half2float(ap[2]) + c2 * __half2float(bp[2]);
        float f3 = c0 * __half2float(hp[3]) + c1 * __half2float(ap[3]) + c2 * __half2float(bp[3]);
        sth2(&hs[r * RW + n4], f0, f1);
        sth2(&hs[r * RW + n4 + 2], f2, f3);
    }
    __syncthreads();

    int mt2 = w & 1, nq = w >> 1;
    {
        float c[4][4];
#pragma unroll
        for (int nt = 0; nt < 4; nt++)
#pragma unroll
            for (int ci = 0; ci < 4; ci++) c[nt][ci] = 0.f;
#pragma unroll
        for (int ks2 = 0; ks2 < 8; ks2++) {
            int off = ks2 * 16;
            const __half* ar0 = hs + (mt2 * 16 + g) * RW + off + 2 * tg;
            const __half* ar1 = ar0 + 8 * RW;
            unsigned a0 = ldh2(ar0), a1 = ldh2(ar1);
            unsigned a2 = ldh2(ar0 + 8), a3 = ldh2(ar1 + 8);
#pragma unroll
            for (int nt = 0; nt < 4; nt++) {
                int nc = nq * 32 + nt * 8 + g;
                const __half* br = ws1 + nc * RW + off + 2 * tg;
                unsigned b0 = ldh2(br), b1 = ldh2(br + 8);
                MMA_F16(c[nt], a0, a1, a2, a3, b0, b1);
            }
        }
#pragma unroll
        for (int nt = 0; nt < 4; nt++) {
            int col0 = nq * 32 + nt * 8 + 2 * tg;
#pragma unroll
            for (int ci2 = 0; ci2 < 2; ci2++) {
                int r = mt2 * 16 + g + ci2 * 8;
                sth2(&hd[r * RW + col0], lrelu(c[nt][ci2 * 2] + cb),
                     lrelu(c[nt][ci2 * 2 + 1] + cb));
            }
        }
    }
    __syncthreads();
    {
        float c[4][4];
#pragma unroll
        for (int nt = 0; nt < 4; nt++)
#pragma unroll
            for (int ci = 0; ci < 4; ci++) c[nt][ci] = 0.f;
#pragma unroll
        for (int ks2 = 0; ks2 < 8; ks2++) {
            int off = ks2 * 16;
            const __half* ar0 = hd + (mt2 * 16 + g) * RW + off + 2 * tg;
            const __half* ar1 = ar0 + 8 * RW;
            unsigned a0 = ldh2(ar0), a1 = ldh2(ar1);
            unsigned a2 = ldh2(ar0 + 8), a3 = ldh2(ar1 + 8);
#pragma unroll
            for (int nt = 0; nt < 4; nt++) {
                int nc = nq * 32 + nt * 8 + g;
                const __half* br = ws2 + nc * RW + off + 2 * tg;
                unsigned b0 = ldh2(br), b1 = ldh2(br + 8);
                MMA_F16(c[nt], a0, a1, a2, a3, b0, b1);
            }
        }
#pragma unroll
        for (int nt = 0; nt < 4; nt++) {
            int col0 = nq * 32 + nt * 8 + 2 * tg;
            float m0 = mbp[col0], m1 = mbp[col0 + 1];
#pragma unroll
            for (int ci2 = 0; ci2 < 2; ci2++) {
                int r = mt2 * 16 + g + ci2 * 8;
                float2 ov = make_float2(c[nt][ci2 * 2] + m0, c[nt][ci2 * 2 + 1] + m1);
                *(float2*)&g_bias2[(size_t)(row0 + r) * DD + col0] = ov;
            }
        }
    }
}

// ---------------- MLP full (layer 0 only) ----------------
#define MLP_O_WS 0
#define MLP_O_H0 17408
#define MLP_O_H1 26112
#define MLP_HALVES 34816
#define MLP_SMEM (MLP_HALVES * 2)
__global__ void __launch_bounds__(256) k_mlp(const float* __restrict__ mw) {
    extern __shared__ unsigned char smraw[];
    __half* ws = (__half*)smraw + MLP_O_WS;
    int tid = threadIdx.x, lane = tid & 31, w = tid >> 5, g = lane >> 2, tg = lane & 3;
    unsigned sb_base = (unsigned)__cvta_generic_to_shared(ws);
    unsigned sb_ws = sb_base;
    unsigned sb_h[2] = {sb_base + MLP_O_H0 * 2, sb_base + MLP_O_H1 * 2};
    unsigned dA = DLA(lane, RW), dB = DLB(lane, RW);

    for (int e = tid; e < 4096; e += 256) {
        int r = e >> 5, k4 = (e & 31) * 4;
        float4 v = *(const float4*)(mw + (size_t)r * 256 + k4);
        sth2(ws + r * RW + k4, v.x, v.y);
        sth2(ws + r * RW + k4 + 2, v.z, v.w);
    }

    int b0 = blockIdx.x * 8;
    {
        int r = tid >> 4, c8 = (tid & 15) * 8;
        const __half* src = g_ret + (size_t)b0 * (TT * DD);
        CP_ASYNC16(sb_h[0] + (r * RW + c8) * 2, src + r * DD + c8);
        CP_ASYNC16(sb_h[0] + ((r + 16) * RW + c8) * 2, src + (r + 16) * DD + c8);
        CP_ASYNC16(sb_h[0] + ((r + 32) * RW + c8) * 2, src + (r + 32) * DD + c8);
        CP_ASYNC16(sb_h[0] + ((r + 48) * RW + c8) * 2, src + (r + 48) * DD + c8);
    }
    CP_COMMIT();

    for (int bi = 0; bi < 8; bi++) {
        int s = b0 + bi;
        int cur = bi & 1;
        CP_WAIT0();
        __syncthreads();
        if (bi < 7) {
            int r = tid >> 4, c8 = (tid & 15) * 8;
            const __half* src = g_ret + (size_t)(s + 1) * (TT * DD);
            unsigned db = sb_h[cur ^ 1];
            CP_ASYNC16(db + (r * RW + c8) * 2, src + r * DD + c8);
            CP_ASYNC16(db + ((r + 16) * RW + c8) * 2, src + (r + 16) * DD + c8);
            CP_ASYNC16(db + ((r + 32) * RW + c8) * 2, src + (r + 32) * DD + c8);
            CP_ASYNC16(db + ((r + 48) * RW + c8) * 2, src + (r + 48) * DD + c8);
        }
        CP_COMMIT();

        float c[4][2][4];
#pragma unroll
        for (int mt = 0; mt < 4; mt++)
#pragma unroll
            for (int nt = 0; nt < 2; nt++)
#pragma unroll
                for (int ci = 0; ci < 4; ci++) c[mt][nt][ci] = 0.f;
#pragma unroll
        for (int ks2 = 0; ks2 < 8; ks2++) {
            int off = ks2 * 16;
            unsigned a[4][4];
#pragma unroll
            for (int mt = 0; mt < 4; mt++)
                ldsmx4(a[mt], sb_h[cur] + ((mt * 16) * RW + off) * 2 + dA);
#pragma unroll
            for (int nt = 0; nt < 2; nt++) {
                unsigned b0r, b1r;
                ldsmx2(b0r, b1r, sb_ws + ((w * 16 + nt * 8) * RW + off) * 2 + dB);
#pragma unroll
                for (int mt = 0; mt < 4; mt++)
                    MMA_F16(c[mt][nt], a[mt][0], a[mt][1], a[mt][2], a[mt][3], b0r, b1r);
            }
        }
        __half* gh = g_h + (size_t)s * (TT * DD);
        const float* bsrc = g_bias2 + (size_t)s * DD;
#pragma unroll
        for (int mt = 0; mt < 4; mt++)
#pragma unroll
            for (int nt = 0; nt < 2; nt++) {
                int col0 = w * 16 + nt * 8 + 2 * tg;
                float2 bv = *(const float2*)&bsrc[col0];
#pragma unroll
                for (int ci2 = 0; ci2 < 2; ci2++) {
                    int r = mt * 16 + g + ci2 * 8;
                    sth2(&gh[r * DD + col0], lrelu(c[mt][nt][ci2 * 2] + bv.x),
                         lrelu(c[mt][nt][ci2 * 2 + 1] + bv.y));
                }
            }
    }
}

// ---------------- MLP last-row only (layer 1): out[s] = lrelu(ret[s][63]@W1^T + bias2[s]) ----------------
__global__ void __launch_bounds__(256, 2) k_mlast(const float* __restrict__ mw) {
    __shared__ __half ws[128 * RW];
    __shared__ __half hs[32 * RW];
    int tid = threadIdx.x, lane = tid & 31, w = tid >> 5, g = lane >> 2, tg = lane & 3;
    int row0 = blockIdx.x * 32;

    for (int e = tid; e < 4096; e += 256) {
        int r = e >> 5, k4 = (e & 31) * 4;
        float4 v = *(const float4*)(mw + (size_t)r * 256 + k4);
        sth2(ws + r * RW + k4, v.x, v.y);
        sth2(ws + r * RW + k4 + 2, v.z, v.w);
    }
    for (int e = tid; e < 512; e += 256) {
        int r = e >> 4, c8 = (e & 15) * 8;
        *(uint4*)(hs + r * RW + c8) =
            *(const uint4*)(g_ret + ((size_t)(row0 + r) * TT + (TT - 1)) * DD + c8);
    }
    __syncthreads();

    int mt2 = w & 1, nq = w >> 1;
    float c[4][4];
#pragma unroll
    for (int nt = 0; nt < 4; nt++)
#pragma unroll
        for (int ci = 0; ci < 4; ci++) c[nt][ci] = 0.f;
#pragma unroll
    for (int ks2 = 0; ks2 < 8; ks2++) {
        int off = ks2 * 16;
        const __half* ar0 = hs + (mt2 * 16 + g) * RW + off + 2 * tg;
        const __half* ar1 = ar0 + 8 * RW;
        unsigned a0 = ldh2(ar0), a1 = ldh2(ar1);
        unsigned a2 = ldh2(ar0 + 8), a3 = ldh2(ar1 + 8);
#pragma unroll
        for (int nt = 0; nt < 4; nt++) {
            int nc = nq * 32 + nt * 8 + g;
            const __half* br = ws + nc * RW + off + 2 * tg;
            unsigned b0 = ldh2(br), b1 = ldh2(br + 8);
            MMA_F16(c[nt], a0, a1, a2, a3, b0, b1);
        }
    }
#pragma unroll
    for (int nt = 0; nt < 4; nt++) {
        int col0 = nq * 32 + nt * 8 + 2 * tg;
#pragma unroll
        for (int ci2 = 0; ci2 < 2; ci2++) {
            int r = mt2 * 16 + g + ci2 * 8;
            float2 bv = *(const float2*)&g_bias2[(size_t)(row0 + r) * DD + col0];
            sth2(&g_lastH[(size_t)(row0 + r) * DD + col0],
                 lrelu(c[nt][ci2 * 2] + bv.x), lrelu(c[nt][ci2 * 2 + 1] + bv.y));
        }
    }
}

// ---------------- head ----------------
__global__ void k_head(const float* __restrict__ h1w, const float* __restrict__ h1b,
                       const float* __restrict__ h2w, const float* __restrict__ h2b,
                       float* __restrict__ out) {
    __shared__ float wt[128 * 65];
    __shared__ float lr[128];
    __shared__ float red[2];
    int bn = blockIdx.x;
    int tid = threadIdx.x;
    for (int e = tid; e < 128; e += 64)
        lr[e] = __half2float(g_lastH[(size_t)bn * DD + e]);
    for (int e = tid; e < 64 * 128; e += 64) {
        int jj = e >> 7, k = e & 127;
        wt[k * 65 + jj] = h1w[e];
    }
    __syncthreads();
    float s = 0.f;
    for (int k = 0; k < 128; k++) s += lr[k] * wt[k * 65 + tid];
    s += h1b[tid];
    s = lrelu(s);
    s *= h2w[tid];
#pragma unroll
    for (int o = 16; o; o >>= 1) s += __shfl_down_sync(0xffffffffu, s, o);
    if ((tid & 31) == 0) red[tid >> 5] = s;
    __syncthreads();
    if (tid == 0) out[bn] = red[0] + red[1] + h2b[0];
}

// ---------------- launch ----------------
extern "C" void kernel_launch(void* const* d_in, const int* in_sizes, int n_in,
                              void* d_out, int out_size) {
    const float* x      = (const float*)d_in[0];
    const float* adj    = (const float*)d_in[1];
    const float* proj_w = (const float*)d_in[2];
    const float* proj_b = (const float*)d_in[3];
    const float* pos    = (const float*)d_in[4];
    const float* diff_w = (const float*)d_in[5];
    const float* conv_w = (const float*)d_in[6];
    const float* conv_b = (const float*)d_in[7];
    const float* wq_w   = (const float*)d_in[8];
    const float* wq_b   = (const float*)d_in[9];
    const float* wk_w   = (const float*)d_in[10];
    const float* wk_b   = (const float*)d_in[11];
    const float* wv_w   = (const float*)d_in[12];
    const float* wv_b   = (const float*)d_in[13];
    const float* gn_w   = (const float*)d_in[14];
    const float* gn_b   = (const float*)d_in[15];
    const float* gamma  = (const float*)d_in[16];
    const float* ln_w   = (const float*)d_in[17];
    const float* ln_b   = (const float*)d_in[18];
    const float* mlp_w  = (const float*)d_in[19];
    const float* mlp_b  = (const float*)d_in[20];
    const float* h1w    = (const float*)d_in[21];
    const float* h1b    = (const float*)d_in[22];
    const float* h2w    = (const float*)d_in[23];
    const float* h2b    = (const float*)d_in[24];

    cudaFuncSetAttribute(k_ret, cudaFuncAttributeMaxDynamicSharedMemorySize, RET_SMEM);
    cudaFuncSetAttribute(k_mlp, cudaFuncAttributeMaxDynamicSharedMemorySize, MLP_SMEM);
    cudaFuncSetAttribute(k_dfin, cudaFuncAttributeMaxDynamicSharedMemorySize, DF_SMEM);

    k_x16<<<BN, 128>>>(x);
    k_adjn<<<BB * NN, 256>>>(adj);
    k_a2<<<dim3(NN / 64, NN / 64, BB), 256>>>();

    for (int l = 0; l < 2; l++) {
        k_ret<<<NSM, 512, RET_SMEM>>>(
            wq_w + l * DD * DD, wq_b + l * DD, wk_w + l * DD * DD, wk_b + l * DD,
            wv_w + l * DD * DD, wv_b + l * DD, gn_w + l * DD, gn_b + l * DD,
            gamma + l, ln_w + l * DD, ln_b + l * DD,
            proj_w, proj_b, pos, l == 0 ? 1 : 0, l == 1 ? 1 : 0);
        k_hopP<<<dim3(NN / 32, BB, 2), 256>>>();
        k_dfin<<<BN / 32, 256, DF_SMEM>>>(diff_w + l * DD * DD,
                                          mlp_w + (size_t)l * DD * 2 * DD,
                                          conv_w + l * 3, conv_b + l, mlp_b + l * DD);
        if (l == 0) {
            k_mlp<<<BN / 8, 256, MLP_SMEM>>>(mlp_w + (size_t)l * DD * 2 * DD);
        } else {
            k_mlast<<<BN / 32, 256>>>(mlp_w + (size_t)l * DD * 2 * DD);
        }
    }
    k_head<<<BN, 64>>>(h1w, h1b, h2w, h2b, (float*)d_out);
}